// round 1
// baseline (speedup 1.0000x reference)
#include <cuda_runtime.h>
#include <math.h>

#define NEL 32
#define NUP 16
#define NI  32
#define NL  16
#define NK  16
#define H1  128
#define H2  4
#define FLEN 392

// Ping-pong state buffers (device globals: no allocation allowed)
__device__ float g_sh[2][NEL][H1];
__device__ float g_dh[2][NEL][NEL][H2];
__device__ float g_rN[NEL][NI];
__device__ float g_phi[NK][2][16][16];
__device__ float g_det[NK][2];

// ---------------------------------------------------------------------------
// Preprocess: electron-nucleus features -> sh0, rN ; electron-electron -> dh0
// ---------------------------------------------------------------------------
__global__ void pre_kernel(const float* __restrict__ ep,
                           const float* __restrict__ nuc) {
    int t = threadIdx.x;
    for (int p = t; p < NEL * NI; p += blockDim.x) {
        int j = p >> 5, m = p & 31;
        float dx = ep[j * 3 + 0] - nuc[m * 3 + 0];
        float dy = ep[j * 3 + 1] - nuc[m * 3 + 1];
        float dz = ep[j * 3 + 2] - nuc[m * 3 + 2];
        float r  = sqrtf(dx * dx + dy * dy + dz * dz);
        g_sh[0][j][m * 3 + 0] = dx;
        g_sh[0][j][m * 3 + 1] = dy;
        g_sh[0][j][m * 3 + 2] = dz;
        g_sh[0][j][3 * NI + m] = r;
        g_rN[j][m] = r;
    }
    for (int p = t; p < NEL * NEL; p += blockDim.x) {
        int i = p >> 5, j = p & 31;
        float dx = ep[i * 3 + 0] - ep[j * 3 + 0];
        float dy = ep[i * 3 + 1] - ep[j * 3 + 1];
        float dz = ep[i * 3 + 2] - ep[j * 3 + 2];
        float r  = sqrtf(dx * dx + dy * dy + dz * dz);
        g_dh[0][i][j][0] = dx;
        g_dh[0][i][j][1] = dy;
        g_dh[0][i][j][2] = dz;
        g_dh[0][i][j][3] = r;
    }
}

// ---------------------------------------------------------------------------
// One layer. Blocks 0..127: single stream (electron n = b>>2, out group b&3).
// Blocks 128..131 (only launched when l < NL-1): double stream.
// ---------------------------------------------------------------------------
__global__ void layer_kernel(const float* __restrict__ v,
                             const float* __restrict__ b,
                             const float* __restrict__ w,
                             const float* __restrict__ c,
                             int l) {
    const int cur = l & 1, nxt = cur ^ 1;
    const int t = threadIdx.x;

    if (blockIdx.x < 128) {
        __shared__ float fsh[FLEN];
        __shared__ float red[256];
        const int n  = blockIdx.x >> 2;
        const int og = blockIdx.x & 3;

        // Build feature vector f = [sh[n] | g_up | g_dn | dg_up[n] | dg_dn[n]]
        if (t < H1) {
            float s = 0.f;
#pragma unroll
            for (int r = 0; r < NUP; r++) s += g_sh[cur][r][t];
            fsh[H1 + t] = s * (1.0f / NUP);
            fsh[t] = g_sh[cur][n][t];
        } else {
            int o = t - H1;
            float s = 0.f;
#pragma unroll
            for (int r = NUP; r < NEL; r++) s += g_sh[cur][r][o];
            fsh[2 * H1 + o] = s * (1.0f / (NEL - NUP));
        }
        if (t < H2) {
            float s = 0.f;
#pragma unroll
            for (int j = 0; j < NUP; j++) s += g_dh[cur][n][j][t];
            fsh[3 * H1 + t] = s * (1.0f / NUP);
        } else if (t < 2 * H2) {
            int d = t - H2;
            float s = 0.f;
#pragma unroll
            for (int j = NUP; j < NEL; j++) s += g_dh[cur][n][j][d];
            fsh[3 * H1 + H2 + d] = s * (1.0f / (NEL - NUP));
        }
        __syncthreads();

        // matvec: o = og*32 + (t&31), reduction split 8 ways over f (t>>5)
        const int ol = t & 31, r = t >> 5;
        const int o = og * 32 + ol;
        const float* vp = v + ((size_t)(l * NEL + n) * FLEN) * H1 + o;

        float a0 = 0.f, a1 = 0.f, a2 = 0.f, a3 = 0.f;
#pragma unroll
        for (int i = 0; i < 48; i += 4) {
            a0 += fsh[r + 8 * (i + 0)] * vp[(size_t)(r + 8 * (i + 0)) * H1];
            a1 += fsh[r + 8 * (i + 1)] * vp[(size_t)(r + 8 * (i + 1)) * H1];
            a2 += fsh[r + 8 * (i + 2)] * vp[(size_t)(r + 8 * (i + 2)) * H1];
            a3 += fsh[r + 8 * (i + 3)] * vp[(size_t)(r + 8 * (i + 3)) * H1];
        }
        a0 += fsh[r + 8 * 48] * vp[(size_t)(r + 8 * 48) * H1];
        red[t] = (a0 + a1) + (a2 + a3);
        __syncthreads();

        if (r == 0) {
            float acc = red[ol];
#pragma unroll
            for (int rr = 1; rr < 8; rr++) acc += red[ol + 32 * rr];
            float val = tanhf(acc + b[(size_t)(l * NEL + n) * H1 + o]) + fsh[o];
            g_sh[nxt][n][o] = val;
        }
    } else {
        // double stream: 1024 (i,j) pairs, tiny 4x4 matvec each
        int pair = (blockIdx.x - 128) * 256 + t;
        int i = pair >> 5, j = pair & 31;
        const float4 d4 = *reinterpret_cast<const float4*>(&g_dh[cur][i][j][0]);
        const float* wp = w + (size_t)((l * NEL + i) * NEL + j) * 16;
        const float* cp = c + (size_t)((l * NEL + i) * NEL + j) * 4;
        float o0 = d4.x * wp[0]  + d4.y * wp[4]  + d4.z * wp[8]  + d4.w * wp[12];
        float o1 = d4.x * wp[1]  + d4.y * wp[5]  + d4.z * wp[9]  + d4.w * wp[13];
        float o2 = d4.x * wp[2]  + d4.y * wp[6]  + d4.z * wp[10] + d4.w * wp[14];
        float o3 = d4.x * wp[3]  + d4.y * wp[7]  + d4.z * wp[11] + d4.w * wp[15];
        float4 out;
        out.x = tanhf(o0 + cp[0]) + d4.x;
        out.y = tanhf(o1 + cp[1]) + d4.y;
        out.z = tanhf(o2 + cp[2]) + d4.z;
        out.w = tanhf(o3 + cp[3]) + d4.w;
        *reinterpret_cast<float4*>(&g_dh[nxt][i][j][0]) = out;
    }
}

// ---------------------------------------------------------------------------
// phi: only the two diagonal 16x16 blocks are needed by the determinants.
// Block = (k, i). 128 threads: 16 j's x 8-way split of dot/env.
// Final sh lives in buffer (NL & 1) == 0.
// ---------------------------------------------------------------------------
__global__ void phi_kernel(const float* __restrict__ fw,
                           const float* __restrict__ fb,
                           const float* __restrict__ pi,
                           const float* __restrict__ sigma) {
    int k = blockIdx.x >> 5;
    int i = blockIdx.x & 31;
    int spin = i >> 4;
    int t = threadIdx.x;
    int jl = t >> 3;      // 0..15
    int s  = t & 7;       // split lane
    int j  = spin * 16 + jl;

    const float* fwp = fw + (size_t)(k * NEL + i) * H1;
    const float* shp = &g_sh[0][j][0];
    float dot = 0.f;
#pragma unroll
    for (int q = 0; q < 16; q++) dot += fwp[s + 8 * q] * shp[s + 8 * q];

    const float* pip = pi + (size_t)(k * NEL + i) * NI;
    const float* sgp = sigma + (size_t)(k * NEL + i) * NI;
    float env = 0.f;
#pragma unroll
    for (int q = 0; q < 4; q++) {
        int m = s * 4 + q;
        env += pip[m] * __expf(-fabsf(sgp[m]) * g_rN[j][m]);
    }
#pragma unroll
    for (int off = 4; off; off >>= 1) {
        dot += __shfl_down_sync(0xffffffffu, dot, off, 8);
        env += __shfl_down_sync(0xffffffffu, env, off, 8);
    }
    if (s == 0)
        g_phi[k][spin][i & 15][jl] = (dot + fb[k * NEL + i]) * env;
}

// ---------------------------------------------------------------------------
// 16x16 determinant via shared-memory LU with partial pivoting.
// Block = (k, spin). 256 threads mapped (r, c).
// ---------------------------------------------------------------------------
__global__ void det_kernel() {
    int k = blockIdx.x >> 1, spin = blockIdx.x & 1;
    __shared__ float A[16][17];
    __shared__ float fac[16];
    __shared__ int   pivs;
    __shared__ float dsh;
    int t = threadIdx.x;
    int r = t >> 4, cc = t & 15;
    A[r][cc] = g_phi[k][spin][r][cc];
    if (t == 0) dsh = 1.0f;
    __syncthreads();
    for (int p = 0; p < 16; p++) {
        if (t == 0) {
            int best = p;
            float bv = fabsf(A[p][p]);
            for (int rr = p + 1; rr < 16; rr++) {
                float v2 = fabsf(A[rr][p]);
                if (v2 > bv) { bv = v2; best = rr; }
            }
            pivs = best;
            if (best != p) dsh = -dsh;
        }
        __syncthreads();
        int piv = pivs;
        if (piv != p && t < 16) {
            float tmp = A[p][t];
            A[p][t] = A[piv][t];
            A[piv][t] = tmp;
        }
        __syncthreads();
        if (t < 16 && t > p) fac[t] = A[t][p] / A[p][p];
        if (t == 0) dsh *= A[p][p];
        __syncthreads();
        if (r > p && cc > p) A[r][cc] -= fac[r] * A[p][cc];
        __syncthreads();
    }
    if (t == 0) g_det[k][spin] = dsh;
}

// ---------------------------------------------------------------------------
// Final reduction: sum_k omega[k] * det_up[k] * det_dn[k]
// ---------------------------------------------------------------------------
__global__ void out_kernel(const float* __restrict__ omega, float* __restrict__ out) {
    int t = threadIdx.x;
    float v = (t < NK) ? omega[t] * g_det[t][0] * g_det[t][1] : 0.0f;
#pragma unroll
    for (int off = 16; off; off >>= 1)
        v += __shfl_down_sync(0xffffffffu, v, off);
    if (t == 0) out[0] = v;
}

extern "C" void kernel_launch(void* const* d_in, const int* in_sizes, int n_in,
                              void* d_out, int out_size) {
    const float* ep    = (const float*)d_in[0];
    const float* nuc   = (const float*)d_in[1];
    const float* v     = (const float*)d_in[2];
    const float* b     = (const float*)d_in[3];
    const float* w     = (const float*)d_in[4];
    const float* c     = (const float*)d_in[5];
    const float* fw    = (const float*)d_in[6];
    const float* fb    = (const float*)d_in[7];
    const float* pi    = (const float*)d_in[8];
    const float* sigma = (const float*)d_in[9];
    const float* omega = (const float*)d_in[10];

    pre_kernel<<<1, 256>>>(ep, nuc);
    for (int l = 0; l < NL; l++) {
        int grid = (l < NL - 1) ? 132 : 128;   // 4 extra blocks do the double stream
        layer_kernel<<<grid, 256>>>(v, b, w, c, l);
    }
    phi_kernel<<<NK * NEL, 128>>>(fw, fb, pi, sigma);
    det_kernel<<<NK * 2, 256>>>();
    out_kernel<<<1, 32>>>(omega, (float*)d_out);
}

// round 2
// speedup vs baseline: 1.6767x; 1.6767x over previous
#include <cuda_runtime.h>
#include <math.h>

#define NEL 32
#define NUP 16
#define NI  32
#define NL  16
#define NK  16
#define H1  128
#define H2  4
#define FLEN 392
#define GRID 128

// Device-global state (no allocations allowed)
__device__ float g_sh[2][NEL][H1];
__device__ float g_dh[2][NEL][NEL][H2];
__device__ float g_rN[NEL][NI];
__device__ float g_phi[NK][2][16][16];
__device__ float g_det[NK][2];
__device__ unsigned g_bar[NL + 2];

// ---------------- acquire/release spin barrier helpers ----------------
__device__ __forceinline__ unsigned ld_acq(const unsigned* p) {
    unsigned v;
    asm volatile("ld.acquire.gpu.global.u32 %0, [%1];" : "=r"(v) : "l"(p) : "memory");
    return v;
}
__device__ __forceinline__ void red_rel_add1(unsigned* p) {
    asm volatile("red.release.gpu.global.add.u32 [%0], 1;" :: "l"(p) : "memory");
}
__device__ __forceinline__ void bar_arrive(int idx) {
    __syncthreads();                       // all block reads/writes done
    if (threadIdx.x == 0) red_rel_add1(&g_bar[idx]);
}
__device__ __forceinline__ void bar_wait(int idx, unsigned target) {
    if (threadIdx.x == 0) {
        while (ld_acq(&g_bar[idx]) < target) { }
    }
    __syncthreads();
}

// ---------------------------------------------------------------------------
// Preprocess: features + rN, and zero the spin-barrier counters (every replay)
// ---------------------------------------------------------------------------
__global__ void pre_kernel(const float* __restrict__ ep,
                           const float* __restrict__ nuc) {
    int t = threadIdx.x;
    if (t < NL + 2) g_bar[t] = 0;
    for (int p = t; p < NEL * NI; p += blockDim.x) {
        int j = p >> 5, m = p & 31;
        float dx = ep[j * 3 + 0] - nuc[m * 3 + 0];
        float dy = ep[j * 3 + 1] - nuc[m * 3 + 1];
        float dz = ep[j * 3 + 2] - nuc[m * 3 + 2];
        float r  = sqrtf(dx * dx + dy * dy + dz * dz);
        g_sh[0][j][m * 3 + 0] = dx;
        g_sh[0][j][m * 3 + 1] = dy;
        g_sh[0][j][m * 3 + 2] = dz;
        g_sh[0][j][3 * NI + m] = r;
        g_rN[j][m] = r;
    }
    for (int p = t; p < NEL * NEL; p += blockDim.x) {
        int i = p >> 5, j = p & 31;
        float dx = ep[i * 3 + 0] - ep[j * 3 + 0];
        float dy = ep[i * 3 + 1] - ep[j * 3 + 1];
        float dz = ep[i * 3 + 2] - ep[j * 3 + 2];
        float r  = sqrtf(dx * dx + dy * dy + dz * dz);
        g_dh[0][i][j][0] = dx;
        g_dh[0][i][j][1] = dy;
        g_dh[0][i][j][2] = dz;
        g_dh[0][i][j][3] = r;
    }
}

// ---------------------------------------------------------------------------
// Persistent fused kernel: 16 layers + phi + det + output.
// 128 blocks (n = b>>2, output quarter og = b&3), 256 threads.
// Weight prefetch for layer l is issued BEFORE waiting on barrier l-1,
// so the 103MB weight stream is continuous across the whole chip.
// ---------------------------------------------------------------------------
__global__ void __launch_bounds__(256, 1) fused_kernel(
    const float* __restrict__ v,  const float* __restrict__ b,
    const float* __restrict__ w,  const float* __restrict__ c,
    const float* __restrict__ fw, const float* __restrict__ fb,
    const float* __restrict__ pi, const float* __restrict__ sigma,
    const float* __restrict__ omega, float* __restrict__ out)
{
    __shared__ float  fsh[FLEN];
    __shared__ float4 part[8][8];
    __shared__ float  A[16][17];
    __shared__ float  fac[16];
    __shared__ int    pivs;
    __shared__ float  dsh;

    const int t   = threadIdx.x;
    const int n   = blockIdx.x >> 2;
    const int og  = blockIdx.x & 3;
    const int c4  = t & 7;       // float4 column within 32-wide output group
    const int fs  = t >> 3;      // 32-way split of the 392 feature rows
    const int lane = t & 31, wrp = t >> 5;

    for (int l = 0; l < NL; l++) {
        // ---- prefetch (independent of activations) ----
        const float* vp = v + (((size_t)l * NEL + n) * FLEN) * H1 + og * 32 + c4 * 4;
        float4 wr[13];
#pragma unroll
        for (int i = 0; i < 12; i++)
            wr[i] = *reinterpret_cast<const float4*>(vp + (size_t)(fs + 32 * i) * H1);
        if (fs < 8)
            wr[12] = *reinterpret_cast<const float4*>(vp + (size_t)(fs + 384) * H1);

        float4 bias;
        if (t < 8)
            bias = *reinterpret_cast<const float4*>(
                b + ((size_t)l * NEL + n) * H1 + og * 32 + t * 4);

        float4 dw0, dw1, dw2, dw3, dc4;
        const int dj = og * 8 + t;           // pair column (valid for t<8)
        if (t < 8 && l < NL - 1) {
            const float* wp = w + ((size_t)(l * NEL + n) * NEL + dj) * 16;
            dw0 = *reinterpret_cast<const float4*>(wp);
            dw1 = *reinterpret_cast<const float4*>(wp + 4);
            dw2 = *reinterpret_cast<const float4*>(wp + 8);
            dw3 = *reinterpret_cast<const float4*>(wp + 12);
            dc4 = *reinterpret_cast<const float4*>(
                c + ((size_t)(l * NEL + n) * NEL + dj) * 4);
        }

        // ---- wait for previous layer outputs ----
        if (l > 0) bar_wait(l - 1, GRID);
        const int cur = l & 1, nxt = cur ^ 1;

        // ---- build feature vector (L2-coherent reads) ----
        if (t < H1) {
            float s = 0.f;
#pragma unroll
            for (int r = 0; r < NUP; r++) s += __ldcg(&g_sh[cur][r][t]);
            fsh[H1 + t] = s * (1.0f / NUP);
            fsh[t] = __ldcg(&g_sh[cur][n][t]);
        } else {
            int o = t - H1;
            float s = 0.f;
#pragma unroll
            for (int r = NUP; r < NEL; r++) s += __ldcg(&g_sh[cur][r][o]);
            fsh[2 * H1 + o] = s * (1.0f / 16);
        }
        if (t < 8) {
            int d  = t & 3;
            int j0 = (t < 4) ? 0 : 16;
            float s = 0.f;
#pragma unroll
            for (int jj = 0; jj < 16; jj++) s += __ldcg(&g_dh[cur][n][j0 + jj][d]);
            fsh[3 * H1 + (t < 4 ? 0 : 4) + d] = s * (1.0f / 16);
        }
        __syncthreads();

        // ---- matvec on prefetched weights ----
        float4 acc = make_float4(0.f, 0.f, 0.f, 0.f);
#pragma unroll
        for (int i = 0; i < 12; i++) {
            float s = fsh[fs + 32 * i];
            acc.x += s * wr[i].x; acc.y += s * wr[i].y;
            acc.z += s * wr[i].z; acc.w += s * wr[i].w;
        }
        if (fs < 8) {
            float s = fsh[fs + 384];
            acc.x += s * wr[12].x; acc.y += s * wr[12].y;
            acc.z += s * wr[12].z; acc.w += s * wr[12].w;
        }
        // intra-warp reduce over the 4 fs values this warp owns
#pragma unroll
        for (int off = 16; off >= 8; off >>= 1) {
            acc.x += __shfl_down_sync(0xffffffffu, acc.x, off);
            acc.y += __shfl_down_sync(0xffffffffu, acc.y, off);
            acc.z += __shfl_down_sync(0xffffffffu, acc.z, off);
            acc.w += __shfl_down_sync(0xffffffffu, acc.w, off);
        }
        if (lane < 8) part[wrp][lane] = acc;
        __syncthreads();

        if (t < 8) {
            float4 a = part[0][t];
#pragma unroll
            for (int ww = 1; ww < 8; ww++) {
                a.x += part[ww][t].x; a.y += part[ww][t].y;
                a.z += part[ww][t].z; a.w += part[ww][t].w;
            }
            int o = og * 32 + t * 4;
            a.x = tanhf(a.x + bias.x) + fsh[o + 0];
            a.y = tanhf(a.y + bias.y) + fsh[o + 1];
            a.z = tanhf(a.z + bias.z) + fsh[o + 2];
            a.w = tanhf(a.w + bias.w) + fsh[o + 3];
            __stcg(reinterpret_cast<float4*>(&g_sh[nxt][n][o]), a);
        }

        // ---- double stream (8 pairs per block) ----
        if (t < 8 && l < NL - 1) {
            float4 d4 = __ldcg(reinterpret_cast<const float4*>(&g_dh[cur][n][dj][0]));
            float o0 = d4.x * dw0.x + d4.y * dw1.x + d4.z * dw2.x + d4.w * dw3.x;
            float o1 = d4.x * dw0.y + d4.y * dw1.y + d4.z * dw2.y + d4.w * dw3.y;
            float o2 = d4.x * dw0.z + d4.y * dw1.z + d4.z * dw2.z + d4.w * dw3.z;
            float o3 = d4.x * dw0.w + d4.y * dw1.w + d4.z * dw2.w + d4.w * dw3.w;
            float4 od;
            od.x = tanhf(o0 + dc4.x) + d4.x;
            od.y = tanhf(o1 + dc4.y) + d4.y;
            od.z = tanhf(o2 + dc4.z) + d4.z;
            od.w = tanhf(o3 + dc4.w) + d4.w;
            __stcg(reinterpret_cast<float4*>(&g_dh[nxt][n][dj][0]), od);
        }
        bar_arrive(l);
    }

    // ================= phi (diagonal 16x16 blocks only) =================
    bar_wait(NL - 1, GRID);
    {
        const int k    = blockIdx.x >> 3;
        const int i    = (blockIdx.x & 7) * 4 + (t >> 6);
        const int spin = i >> 4;
        const int tl   = t & 63;
        const int jl   = tl >> 2, s = tl & 3;
        const int j    = spin * 16 + jl;
        const float* fwp = fw + (size_t)(k * NEL + i) * H1;
        float dot = 0.f;
#pragma unroll
        for (int q = 0; q < 32; q++)
            dot += fwp[s + 4 * q] * __ldcg(&g_sh[0][j][s + 4 * q]);
        const float* pip = pi    + (size_t)(k * NEL + i) * NI;
        const float* sgp = sigma + (size_t)(k * NEL + i) * NI;
        float env = 0.f;
#pragma unroll
        for (int q = 0; q < 8; q++) {
            int m = s * 8 + q;
            env += pip[m] * __expf(-fabsf(sgp[m]) * g_rN[j][m]);
        }
        dot += __shfl_down_sync(0xffffffffu, dot, 2, 4);
        dot += __shfl_down_sync(0xffffffffu, dot, 1, 4);
        env += __shfl_down_sync(0xffffffffu, env, 2, 4);
        env += __shfl_down_sync(0xffffffffu, env, 1, 4);
        if (s == 0)
            __stcg(&g_phi[k][spin][i & 15][jl], (dot + fb[k * NEL + i]) * env);
    }
    bar_arrive(NL);

    // ================= determinants (blocks 0..31) =================
    if (blockIdx.x < 32) {
        bar_wait(NL, GRID);
        const int k = blockIdx.x >> 1, spin = blockIdx.x & 1;
        const int r = t >> 4, cc = t & 15;
        A[r][cc] = __ldcg(&g_phi[k][spin][r][cc]);
        if (t == 0) dsh = 1.0f;
        __syncthreads();
        for (int p = 0; p < 16; p++) {
            if (t == 0) {
                int best = p;
                float bv = fabsf(A[p][p]);
                for (int rr = p + 1; rr < 16; rr++) {
                    float v2 = fabsf(A[rr][p]);
                    if (v2 > bv) { bv = v2; best = rr; }
                }
                pivs = best;
                if (best != p) dsh = -dsh;
            }
            __syncthreads();
            int piv = pivs;
            if (piv != p && t < 16) {
                float tmp = A[p][t]; A[p][t] = A[piv][t]; A[piv][t] = tmp;
            }
            __syncthreads();
            if (t < 16 && t > p) fac[t] = A[t][p] / A[p][p];
            if (t == 0) dsh *= A[p][p];
            __syncthreads();
            if (r > p && cc > p) A[r][cc] -= fac[r] * A[p][cc];
            __syncthreads();
        }
        if (t == 0) __stcg(&g_det[k][spin], dsh);
        bar_arrive(NL + 1);
    }

    // ================= final reduction (block 0) =================
    if (blockIdx.x == 0) {
        bar_wait(NL + 1, 32);
        if (t < 32) {
            float vv = (t < NK) ? omega[t] * __ldcg(&g_det[t][0]) * __ldcg(&g_det[t][1])
                                : 0.0f;
#pragma unroll
            for (int off = 16; off; off >>= 1)
                vv += __shfl_down_sync(0xffffffffu, vv, off);
            if (t == 0) out[0] = vv;
        }
    }
}

extern "C" void kernel_launch(void* const* d_in, const int* in_sizes, int n_in,
                              void* d_out, int out_size) {
    const float* ep    = (const float*)d_in[0];
    const float* nuc   = (const float*)d_in[1];
    const float* v     = (const float*)d_in[2];
    const float* b     = (const float*)d_in[3];
    const float* w     = (const float*)d_in[4];
    const float* c     = (const float*)d_in[5];
    const float* fw    = (const float*)d_in[6];
    const float* fb    = (const float*)d_in[7];
    const float* pi    = (const float*)d_in[8];
    const float* sigma = (const float*)d_in[9];
    const float* omega = (const float*)d_in[10];

    pre_kernel<<<1, 256>>>(ep, nuc);
    fused_kernel<<<GRID, 256>>>(v, b, w, c, fw, fb, pi, sigma, omega, (float*)d_out);
}